// round 15
// baseline (speedup 1.0000x reference)
#include <cuda_runtime.h>
#include <cuda_bf16.h>

#define MAX_CTA 4096
__device__ float g_cta_sum[MAX_CTA];
__device__ int   g_done_ctr = 0;

// ---------------------------------------------------------------------------
// Two warps per row on CONTIGUOUS halves of the valid prefix, direct LDG.
//   warp w -> row w>>1, half w&1; half 0 = chunks [0,Vh), half 1 = [Vh,V),
//   Vh = (V+1)/2. Same proven batched 8-LDG hot loop as the 10.7us kernel,
//   but max per-warp chain is halved (256 chunks) and warp count doubled
//   (8192) -> shorter serial chains, smaller straggler tail.
//   loss = (1/B) * sum_row (1/L) * sum_{t<L} (pred - log(align))^2
// Deterministic: static ownership, fixed accumulation & reduce order.
// ---------------------------------------------------------------------------
template <int BLOCK>
__global__ void dploss_half2_kernel(const float* __restrict__ pred,
                                    const float* __restrict__ align,
                                    const int* __restrict__ lens,
                                    float* __restrict__ out,
                                    int C, int B, int nCta) {
    const int lane = threadIdx.x & 31;
    const int wic  = threadIdx.x >> 5;                 // warp in CTA (0..3)
    const int w    = (blockIdx.x * BLOCK + threadIdx.x) >> 5;

    float acc = 0.0f;

    const int row = w >> 1;
    if (row < B) {
        const int half = w & 1;
        const int L  = __ldg(lens + row);
        const int nfull = L >> 2;                      // fully-valid chunks
        const int V  = (L + 3) >> 2;                   // valid chunks
        const int Vh = (V + 1) >> 1;
        const int s0 = half ? Vh : 0;
        const int s1 = half ? V  : Vh;

        const size_t base = (size_t)row * (size_t)C;
        const float4* __restrict__ p4 = reinterpret_cast<const float4*>(pred) + base;
        const float4* __restrict__ a4 = reinterpret_cast<const float4*>(align) + base;

        const int fullEnd = min(s1, nfull);
        float t0 = 0.0f, t1 = 0.0f, t2 = 0.0f, t3 = 0.0f;

        int c = s0 + lane;
        // Hot loop: 4 full chunks / iter, 8 independent LDG.128 batched.
        for (; c + 96 < fullEnd; c += 128) {
            float4 pA = p4[c];
            float4 aA = a4[c];
            float4 pB = p4[c + 32];
            float4 aB = a4[c + 32];
            float4 pC = p4[c + 64];
            float4 aC = a4[c + 64];
            float4 pD = p4[c + 96];
            float4 aD = a4[c + 96];
            float d;
            d = pA.x - __logf(aA.x); t0 = fmaf(d, d, t0);
            d = pA.y - __logf(aA.y); t0 = fmaf(d, d, t0);
            d = pA.z - __logf(aA.z); t0 = fmaf(d, d, t0);
            d = pA.w - __logf(aA.w); t0 = fmaf(d, d, t0);
            d = pB.x - __logf(aB.x); t1 = fmaf(d, d, t1);
            d = pB.y - __logf(aB.y); t1 = fmaf(d, d, t1);
            d = pB.z - __logf(aB.z); t1 = fmaf(d, d, t1);
            d = pB.w - __logf(aB.w); t1 = fmaf(d, d, t1);
            d = pC.x - __logf(aC.x); t2 = fmaf(d, d, t2);
            d = pC.y - __logf(aC.y); t2 = fmaf(d, d, t2);
            d = pC.z - __logf(aC.z); t2 = fmaf(d, d, t2);
            d = pC.w - __logf(aC.w); t2 = fmaf(d, d, t2);
            d = pD.x - __logf(aD.x); t3 = fmaf(d, d, t3);
            d = pD.y - __logf(aD.y); t3 = fmaf(d, d, t3);
            d = pD.z - __logf(aD.z); t3 = fmaf(d, d, t3);
            d = pD.w - __logf(aD.w); t3 = fmaf(d, d, t3);
        }
        // Remaining full chunks.
        for (; c < fullEnd; c += 32) {
            float4 p = p4[c];
            float4 a = a4[c];
            float d;
            d = p.x - __logf(a.x); t0 = fmaf(d, d, t0);
            d = p.y - __logf(a.y); t1 = fmaf(d, d, t1);
            d = p.z - __logf(a.z); t2 = fmaf(d, d, t2);
            d = p.w - __logf(a.w); t3 = fmaf(d, d, t3);
        }
        // Partial tail chunk (index nfull, 1..3 valid elems) if in my half.
        // Safe read: L&3 != 0 implies L < T, so chunk nfull < C.
        if ((L & 3) && nfull >= s0 && nfull < s1 && lane == (nfull & 31)) {
            float4 p = p4[nfull];
            float4 a = a4[nfull];
            int rem = L & 3;
            float d;
            d = p.x - __logf(a.x); t0 = fmaf(d, d, t0);
            if (rem > 1) { d = p.y - __logf(a.y); t1 = fmaf(d, d, t1); }
            if (rem > 2) { d = p.z - __logf(a.z); t2 = fmaf(d, d, t2); }
        }

        acc = ((t0 + t1) + (t2 + t3)) * __frcp_rn((float)L);
    }

    // Warp reduction (fixed order -> deterministic).
    #pragma unroll
    for (int off = 16; off > 0; off >>= 1)
        acc += __shfl_down_sync(0xFFFFFFFFu, acc, off);

    // Per-CTA partial (fixed order over 4 warps).
    __shared__ float s_w[BLOCK / 32];
    if (lane == 0) s_w[wic] = acc;
    __syncthreads();

    __shared__ bool s_is_last;
    if (threadIdx.x == 0) {
        float v = 0.0f;
        #pragma unroll
        for (int k = 0; k < BLOCK / 32; k++) v += s_w[k];
        g_cta_sum[blockIdx.x] = v;
        __threadfence();
        int old = atomicAdd(&g_done_ctr, 1);
        s_is_last = (old == nCta - 1);
    }
    __syncthreads();

    if (s_is_last) {
        float v = 0.0f;
        for (int i = threadIdx.x; i < nCta; i += BLOCK)  // fixed strided order
            v += g_cta_sum[i];
        __shared__ float s_fin[BLOCK / 32];
        #pragma unroll
        for (int off = 16; off > 0; off >>= 1)
            v += __shfl_down_sync(0xFFFFFFFFu, v, off);
        if (lane == 0) s_fin[wic] = v;
        __syncthreads();
        if (threadIdx.x == 0) {
            float t = 0.0f;
            #pragma unroll
            for (int k = 0; k < BLOCK / 32; k++) t += s_fin[k];
            out[0] = t / (float)B;
            g_done_ctr = 0;                   // reset for next graph replay
        }
    }
}

extern "C" void kernel_launch(void* const* d_in, const int* in_sizes, int n_in,
                              void* d_out, int out_size) {
    const float* pred  = (const float*)d_in[0];
    const float* align = (const float*)d_in[1];
    const int*   lens  = (const int*)d_in[2];
    float* out = (float*)d_out;

    const int B = in_sizes[2];
    const int T = in_sizes[0] / B;
    const int C = T >> 2;

    constexpr int BLOCK = 128;                 // 4 warps per CTA
    int grid = (B * 2 + (BLOCK / 32) - 1) / (BLOCK / 32);   // 2 warps per row
    if (grid > MAX_CTA) grid = MAX_CTA;
    if (grid < 1) grid = 1;

    dploss_half2_kernel<BLOCK><<<grid, BLOCK>>>(pred, align, lens, out,
                                                C, B, grid);
}

// round 16
// speedup vs baseline: 1.0222x; 1.0222x over previous
#include <cuda_runtime.h>
#include <cuda_bf16.h>

#define MAX_B 8192
__device__ float g_row_mse[MAX_B];
__device__ int   g_done_ctr = 0;

__device__ __forceinline__ void pf_l1(const void* p) {
    asm volatile("prefetch.global.L1 [%0];" :: "l"(p));
}

// ---------------------------------------------------------------------------
// Warp-per-row (the proven 10.7us structure) + software prefetch.
// Each warp owns one full row and streams its valid prefix with the batched
// 8-LDG hot loop; each lane additionally PREFETCHES its chunk 2 iterations
// ahead (+256 chunks) into L1 -- no destination registers, no smem, no waits.
// The real loads then hit L1 (~39cyc) instead of L2 (~240cyc)/DRAM.
//   loss = (1/B) * sum_row (1/L) * sum_{t<L} (pred - log(align))^2
// Deterministic: static ownership, fixed accumulation & reduce order.
// ---------------------------------------------------------------------------
template <int BLOCK>
__global__ void dploss_pf_kernel(const float* __restrict__ pred,
                                 const float* __restrict__ align,
                                 const int* __restrict__ lens,
                                 float* __restrict__ out,
                                 int C, int B) {
    const int lane = threadIdx.x & 31;
    const int warpsPerGrid = (gridDim.x * BLOCK) >> 5;
    const int warpId = (blockIdx.x * BLOCK + threadIdx.x) >> 5;

    for (int row = warpId; row < B; row += warpsPerGrid) {
        const int L = __ldg(lens + row);          // one lens load per row
        const int nfull = L >> 2;                 // fully-valid chunks
        const size_t base = (size_t)row * (size_t)C;
        const float4* __restrict__ p4 = reinterpret_cast<const float4*>(pred) + base;
        const float4* __restrict__ a4 = reinterpret_cast<const float4*>(align) + base;

        float s0 = 0.0f, s1 = 0.0f, s2 = 0.0f, s3 = 0.0f;

        // Warm the first two iterations' lines.
        if (lane + 128 < nfull) { pf_l1(p4 + lane); pf_l1(a4 + lane); }

        int c = lane;
        // Hot loop: 4 full chunks / iter, 8 independent LDG.128 batched,
        // plus prefetch of the iteration after next.
        for (; c + 96 < nfull; c += 128) {
            // Prefetch 2 iterations ahead (PTX prefetch never faults -> no guard).
            pf_l1(p4 + c + 256);
            pf_l1(a4 + c + 256);

            float4 pA = p4[c];
            float4 aA = a4[c];
            float4 pB = p4[c + 32];
            float4 aB = a4[c + 32];
            float4 pC = p4[c + 64];
            float4 aC = a4[c + 64];
            float4 pD = p4[c + 96];
            float4 aD = a4[c + 96];

            float d;
            d = pA.x - __logf(aA.x); s0 = fmaf(d, d, s0);
            d = pA.y - __logf(aA.y); s0 = fmaf(d, d, s0);
            d = pA.z - __logf(aA.z); s0 = fmaf(d, d, s0);
            d = pA.w - __logf(aA.w); s0 = fmaf(d, d, s0);
            d = pB.x - __logf(aB.x); s1 = fmaf(d, d, s1);
            d = pB.y - __logf(aB.y); s1 = fmaf(d, d, s1);
            d = pB.z - __logf(aB.z); s1 = fmaf(d, d, s1);
            d = pB.w - __logf(aB.w); s1 = fmaf(d, d, s1);
            d = pC.x - __logf(aC.x); s2 = fmaf(d, d, s2);
            d = pC.y - __logf(aC.y); s2 = fmaf(d, d, s2);
            d = pC.z - __logf(aC.z); s2 = fmaf(d, d, s2);
            d = pC.w - __logf(aC.w); s2 = fmaf(d, d, s2);
            d = pD.x - __logf(aD.x); s3 = fmaf(d, d, s3);
            d = pD.y - __logf(aD.y); s3 = fmaf(d, d, s3);
            d = pD.z - __logf(aD.z); s3 = fmaf(d, d, s3);
            d = pD.w - __logf(aD.w); s3 = fmaf(d, d, s3);
        }
        // Remaining full chunks.
        for (; c < nfull; c += 32) {
            float4 p = p4[c];
            float4 a = a4[c];
            float d;
            d = p.x - __logf(a.x); s0 = fmaf(d, d, s0);
            d = p.y - __logf(a.y); s1 = fmaf(d, d, s1);
            d = p.z - __logf(a.z); s2 = fmaf(d, d, s2);
            d = p.w - __logf(a.w); s3 = fmaf(d, d, s3);
        }
        // Partial tail chunk (1..3 valid elems); owned by one lane.
        // Safe read: L&3 != 0 implies L < T, so chunk nfull < C.
        if ((L & 3) && lane == (nfull & 31)) {
            float4 p = p4[nfull];
            float4 a = a4[nfull];
            int rem = L & 3;
            float d;
            d = p.x - __logf(a.x); s0 = fmaf(d, d, s0);
            if (rem > 1) { d = p.y - __logf(a.y); s1 = fmaf(d, d, s1); }
            if (rem > 2) { d = p.z - __logf(a.z); s2 = fmaf(d, d, s2); }
        }

        float s = (s0 + s1) + (s2 + s3);
        // Warp reduction (fixed order -> deterministic).
        #pragma unroll
        for (int off = 16; off > 0; off >>= 1)
            s += __shfl_down_sync(0xFFFFFFFFu, s, off);
        if (lane == 0)
            g_row_mse[row] = s * __frcp_rn((float)L);
    }

    // Completion signal; last CTA reduces all rows in fixed order.
    __syncthreads();
    __shared__ bool s_is_last;
    if (threadIdx.x == 0) {
        __threadfence();
        int old = atomicAdd(&g_done_ctr, 1);
        s_is_last = (old == (int)gridDim.x - 1);
    }
    __syncthreads();

    if (s_is_last) {
        float v = 0.0f;
        for (int i = threadIdx.x; i < B; i += BLOCK)   // fixed strided order
            v += g_row_mse[i];
        __shared__ float warp_sums[BLOCK / 32];
        #pragma unroll
        for (int off = 16; off > 0; off >>= 1)
            v += __shfl_down_sync(0xFFFFFFFFu, v, off);
        if ((threadIdx.x & 31) == 0)
            warp_sums[threadIdx.x >> 5] = v;
        __syncthreads();
        if (threadIdx.x == 0) {
            float t = 0.0f;
            #pragma unroll
            for (int w = 0; w < BLOCK / 32; w++)
                t += warp_sums[w];
            out[0] = t / (float)B;
            g_done_ctr = 0;   // reset for next graph replay
        }
    }
}

extern "C" void kernel_launch(void* const* d_in, const int* in_sizes, int n_in,
                              void* d_out, int out_size) {
    const float* pred  = (const float*)d_in[0];
    const float* align = (const float*)d_in[1];
    const int*   lens  = (const int*)d_in[2];
    float* out = (float*)d_out;

    const int B = in_sizes[2];
    const int T = in_sizes[0] / B;
    const int C = T >> 2;

    constexpr int BLOCK = 128;                     // 4 warps per CTA
    int grid = (B + (BLOCK / 32) - 1) / (BLOCK / 32);  // one warp per row
    if (grid < 1) grid = 1;
    if (grid > 4096) grid = 4096;

    dploss_pf_kernel<BLOCK><<<grid, BLOCK>>>(pred, align, lens, out, C, B);
}

// round 17
// speedup vs baseline: 1.2064x; 1.1802x over previous
#include <cuda_runtime.h>
#include <cuda_bf16.h>

#define MAX_CTA 4096
__device__ float g_cta_sum[MAX_CTA];
__device__ int   g_done_ctr = 0;

// log2-space constants: p - ln(a) = ln2 * (p*K - log2(a));  sum d^2 scales by LN2SQ.
#define K_RLN2 1.4426950408889634f
#define LN2SQ  0.4804530139182014f

__device__ __forceinline__ float lg2f(float x) {
    float r;
    asm("lg2.approx.f32 %0, %1;" : "=f"(r) : "f"(x));
    return r;
}

// ---------------------------------------------------------------------------
// Warp-per-row (the proven 10.7us structure), minimized instruction count.
// Hot loop per element: MUFU.LG2 + FFMA(p*K - lg) + FFMA(acc) — 3 instrs vs 4.
//   loss = (1/B) * sum_row (LN2SQ/L) * sum_{t<L} (pred*K - log2(align))^2
// Deterministic: static ownership, fixed accumulation & reduce order.
// ---------------------------------------------------------------------------
template <int BLOCK>
__global__ void dploss_lg2_kernel(const float* __restrict__ pred,
                                  const float* __restrict__ align,
                                  const int* __restrict__ lens,
                                  float* __restrict__ out,
                                  int C, int B, int nCta) {
    const int lane = threadIdx.x & 31;
    const int wic  = threadIdx.x >> 5;
    const int warpsPerGrid = (gridDim.x * BLOCK) >> 5;
    const int warpId = (blockIdx.x * BLOCK + threadIdx.x) >> 5;

    float wacc = 0.0f;

    for (int row = warpId; row < B; row += warpsPerGrid) {
        const int L = __ldg(lens + row);
        const int nfull = L >> 2;
        const size_t base = (size_t)row * (size_t)C;
        const float4* __restrict__ p4 = reinterpret_cast<const float4*>(pred) + base;
        const float4* __restrict__ a4 = reinterpret_cast<const float4*>(align) + base;

        float s0 = 0.0f, s1 = 0.0f, s2 = 0.0f, s3 = 0.0f;

        int c = lane;
        // Hot loop: 4 full chunks / iter, 8 independent LDG.128 batched.
        for (; c + 96 < nfull; c += 128) {
            float4 pA = p4[c];
            float4 aA = a4[c];
            float4 pB = p4[c + 32];
            float4 aB = a4[c + 32];
            float4 pC = p4[c + 64];
            float4 aC = a4[c + 64];
            float4 pD = p4[c + 96];
            float4 aD = a4[c + 96];

            float d;
            d = __fmaf_rn(pA.x, K_RLN2, -lg2f(aA.x)); s0 = __fmaf_rn(d, d, s0);
            d = __fmaf_rn(pA.y, K_RLN2, -lg2f(aA.y)); s0 = __fmaf_rn(d, d, s0);
            d = __fmaf_rn(pA.z, K_RLN2, -lg2f(aA.z)); s0 = __fmaf_rn(d, d, s0);
            d = __fmaf_rn(pA.w, K_RLN2, -lg2f(aA.w)); s0 = __fmaf_rn(d, d, s0);
            d = __fmaf_rn(pB.x, K_RLN2, -lg2f(aB.x)); s1 = __fmaf_rn(d, d, s1);
            d = __fmaf_rn(pB.y, K_RLN2, -lg2f(aB.y)); s1 = __fmaf_rn(d, d, s1);
            d = __fmaf_rn(pB.z, K_RLN2, -lg2f(aB.z)); s1 = __fmaf_rn(d, d, s1);
            d = __fmaf_rn(pB.w, K_RLN2, -lg2f(aB.w)); s1 = __fmaf_rn(d, d, s1);
            d = __fmaf_rn(pC.x, K_RLN2, -lg2f(aC.x)); s2 = __fmaf_rn(d, d, s2);
            d = __fmaf_rn(pC.y, K_RLN2, -lg2f(aC.y)); s2 = __fmaf_rn(d, d, s2);
            d = __fmaf_rn(pC.z, K_RLN2, -lg2f(aC.z)); s2 = __fmaf_rn(d, d, s2);
            d = __fmaf_rn(pC.w, K_RLN2, -lg2f(aC.w)); s2 = __fmaf_rn(d, d, s2);
            d = __fmaf_rn(pD.x, K_RLN2, -lg2f(aD.x)); s3 = __fmaf_rn(d, d, s3);
            d = __fmaf_rn(pD.y, K_RLN2, -lg2f(aD.y)); s3 = __fmaf_rn(d, d, s3);
            d = __fmaf_rn(pD.z, K_RLN2, -lg2f(aD.z)); s3 = __fmaf_rn(d, d, s3);
            d = __fmaf_rn(pD.w, K_RLN2, -lg2f(aD.w)); s3 = __fmaf_rn(d, d, s3);
        }
        // Remaining full chunks.
        for (; c < nfull; c += 32) {
            float4 p = p4[c];
            float4 a = a4[c];
            float d;
            d = __fmaf_rn(p.x, K_RLN2, -lg2f(a.x)); s0 = __fmaf_rn(d, d, s0);
            d = __fmaf_rn(p.y, K_RLN2, -lg2f(a.y)); s1 = __fmaf_rn(d, d, s1);
            d = __fmaf_rn(p.z, K_RLN2, -lg2f(a.z)); s2 = __fmaf_rn(d, d, s2);
            d = __fmaf_rn(p.w, K_RLN2, -lg2f(a.w)); s3 = __fmaf_rn(d, d, s3);
        }
        // Partial tail chunk (1..3 valid elems); owned by one lane.
        // Safe read: L&3 != 0 implies L < T, so chunk nfull < C.
        if ((L & 3) && lane == (nfull & 31)) {
            float4 p = p4[nfull];
            float4 a = a4[nfull];
            int rem = L & 3;
            float d;
            d = __fmaf_rn(p.x, K_RLN2, -lg2f(a.x)); s0 = __fmaf_rn(d, d, s0);
            if (rem > 1) { d = __fmaf_rn(p.y, K_RLN2, -lg2f(a.y)); s1 = __fmaf_rn(d, d, s1); }
            if (rem > 2) { d = __fmaf_rn(p.z, K_RLN2, -lg2f(a.z)); s2 = __fmaf_rn(d, d, s2); }
        }

        float s = (s0 + s1) + (s2 + s3);
        // Warp reduction (fixed order -> deterministic).
        #pragma unroll
        for (int off = 16; off > 0; off >>= 1)
            s += __shfl_down_sync(0xFFFFFFFFu, s, off);
        // ln2^2 and 1/L folded into one per-row weight.
        wacc += s * (LN2SQ * __frcp_rn((float)L));
    }

    // Per-CTA partial (fixed order over 4 warps) -> 4x fewer final loads.
    __shared__ float s_w[BLOCK / 32];
    if (lane == 0) s_w[wic] = wacc;
    __syncthreads();

    __shared__ bool s_is_last;
    if (threadIdx.x == 0) {
        float v = 0.0f;
        #pragma unroll
        for (int k = 0; k < BLOCK / 32; k++) v += s_w[k];
        g_cta_sum[blockIdx.x] = v;
        __threadfence();
        int old = atomicAdd(&g_done_ctr, 1);
        s_is_last = (old == nCta - 1);
    }
    __syncthreads();

    if (s_is_last) {
        float v = 0.0f;
        for (int i = threadIdx.x; i < nCta; i += BLOCK)   // fixed strided order
            v += g_cta_sum[i];
        __shared__ float s_fin[BLOCK / 32];
        #pragma unroll
        for (int off = 16; off > 0; off >>= 1)
            v += __shfl_down_sync(0xFFFFFFFFu, v, off);
        if (lane == 0) s_fin[wic] = v;
        __syncthreads();
        if (threadIdx.x == 0) {
            float t = 0.0f;
            #pragma unroll
            for (int k = 0; k < BLOCK / 32; k++) t += s_fin[k];
            out[0] = t / (float)B;
            g_done_ctr = 0;   // reset for next graph replay
        }
    }
}

extern "C" void kernel_launch(void* const* d_in, const int* in_sizes, int n_in,
                              void* d_out, int out_size) {
    const float* pred  = (const float*)d_in[0];
    const float* align = (const float*)d_in[1];
    const int*   lens  = (const int*)d_in[2];
    float* out = (float*)d_out;

    const int B = in_sizes[2];
    const int T = in_sizes[0] / B;
    const int C = T >> 2;

    constexpr int BLOCK = 128;                     // 4 warps per CTA
    int grid = (B + (BLOCK / 32) - 1) / (BLOCK / 32);  // one warp per row
    if (grid < 1) grid = 1;
    if (grid > MAX_CTA) grid = MAX_CTA;

    dploss_lg2_kernel<BLOCK><<<grid, BLOCK>>>(pred, align, lens, out, C, B, grid);
}